// round 1
// baseline (speedup 1.0000x reference)
#include <cuda_runtime.h>
#include <math.h>

#define B_ 2
#define S_ 2048
#define E_ 2048
#define H_ 32
#define D_ 64
#define M_ (B_*S_)
#define SCALE_ 0.125f

// Scratch (static device allocations are allowed; runtime allocs are not)
static __device__ float g_q[(size_t)M_ * E_];
static __device__ float g_k[(size_t)M_ * E_];
static __device__ float g_v[(size_t)M_ * E_];
static __device__ float g_attn[(size_t)M_ * E_];

// ---------------------------------------------------------------------------
// SGEMM: C[m,n] = sum_k A[m,k] * Bm[n,k] + bias[n]
// A: [M,K] row-major, Bm: [N,K] row-major (i.e. computes A @ Bm^T + bias)
// 128x128 tile, BK=8, 256 threads, 8x8 microtile per thread.
// ---------------------------------------------------------------------------
__global__ __launch_bounds__(256) void sgemm_bias(
    const float* __restrict__ A, const float* __restrict__ Bm,
    const float* __restrict__ bias, float* __restrict__ C,
    int M, int N, int K)
{
    __shared__ float As[8][128];
    __shared__ float Bs[8][128];

    const int t  = threadIdx.x;
    const int tx = t & 15;      // 0..15 -> n micro
    const int ty = t >> 4;      // 0..15 -> m micro
    const int m0 = blockIdx.y * 128;
    const int n0 = blockIdx.x * 128;

    const int lr = t >> 1;          // 0..127 row within tile
    const int lk = (t & 1) * 4;     // 0 or 4

    const float* Ap = A  + (size_t)(m0 + lr) * K + lk;
    const float* Bp = Bm + (size_t)(n0 + lr) * K + lk;

    float acc[8][8];
#pragma unroll
    for (int i = 0; i < 8; i++)
#pragma unroll
        for (int j = 0; j < 8; j++) acc[i][j] = 0.f;

    for (int k0 = 0; k0 < K; k0 += 8) {
        float4 a4 = *(const float4*)(Ap + k0);
        float4 b4 = *(const float4*)(Bp + k0);
        __syncthreads();
        As[lk + 0][lr] = a4.x; As[lk + 1][lr] = a4.y;
        As[lk + 2][lr] = a4.z; As[lk + 3][lr] = a4.w;
        Bs[lk + 0][lr] = b4.x; Bs[lk + 1][lr] = b4.y;
        Bs[lk + 2][lr] = b4.z; Bs[lk + 3][lr] = b4.w;
        __syncthreads();
#pragma unroll
        for (int kk = 0; kk < 8; kk++) {
            float ra[8], rb[8];
#pragma unroll
            for (int i = 0; i < 8; i++) ra[i] = As[kk][ty * 8 + i];
#pragma unroll
            for (int j = 0; j < 8; j++) rb[j] = Bs[kk][tx * 8 + j];
#pragma unroll
            for (int i = 0; i < 8; i++)
#pragma unroll
                for (int j = 0; j < 8; j++)
                    acc[i][j] = fmaf(ra[i], rb[j], acc[i][j]);
        }
    }

    float bv[8];
#pragma unroll
    for (int j = 0; j < 8; j++) bv[j] = bias[n0 + tx * 8 + j];

#pragma unroll
    for (int i = 0; i < 8; i++) {
        float4 o0, o1;
        o0.x = acc[i][0] + bv[0]; o0.y = acc[i][1] + bv[1];
        o0.z = acc[i][2] + bv[2]; o0.w = acc[i][3] + bv[3];
        o1.x = acc[i][4] + bv[4]; o1.y = acc[i][5] + bv[5];
        o1.z = acc[i][6] + bv[6]; o1.w = acc[i][7] + bv[7];
        size_t off = (size_t)(m0 + ty * 8 + i) * N + n0 + tx * 8;
        *(float4*)(C + off)     = o0;
        *(float4*)(C + off + 4) = o1;
    }
}

// ---------------------------------------------------------------------------
// Flash attention (causal), fp32.
// Q/K/V layout: [B, S, H*D] (head h occupies columns h*64..h*64+63).
// Block: one (b,h) pair x 64-query tile. 256 threads, 16x16 thread grid,
// each thread owns a 4(query)x4 micro-tile of scores and a 4(query)x4(d)
// micro-tile of the output accumulator. Online softmax state (m,l) is
// register-replicated across the 16 lanes of each row group (no smem races).
// ---------------------------------------------------------------------------
#define AT_PAD 68

__global__ __launch_bounds__(256) void flash_attn(
    const float* __restrict__ Q, const float* __restrict__ Kt,
    const float* __restrict__ V, float* __restrict__ O)
{
    extern __shared__ float smem[];
    float* sQ = smem;                   // 64*68
    float* sK = sQ + 64 * AT_PAD;       // 64*68
    float* sV = sK + 64 * AT_PAD;       // 64*68
    float* sP = sV + 64 * AT_PAD;       // 64*68

    const int t  = threadIdx.x;
    const int tx = t & 15;
    const int ty = t >> 4;
    const int qt = blockIdx.x;          // query tile (0..31)
    const int bh = blockIdx.y;          // b*H + h
    const int b  = bh / H_;
    const int h  = bh % H_;
    const int q0 = qt * 64;

    const size_t base = ((size_t)b * S_) * E_ + (size_t)h * D_;

    // Load Q tile (coalesced float4)
#pragma unroll
    for (int it = 0; it < 4; it++) {
        int idx = t + it * 256;         // 0..1023
        int r   = idx >> 4;             // 0..63
        int d4  = (idx & 15) * 4;
        float4 qv = *(const float4*)(Q + base + (size_t)(q0 + r) * E_ + d4);
        sQ[r * AT_PAD + d4 + 0] = qv.x;
        sQ[r * AT_PAD + d4 + 1] = qv.y;
        sQ[r * AT_PAD + d4 + 2] = qv.z;
        sQ[r * AT_PAD + d4 + 3] = qv.w;
    }

    float Oacc[4][4];
#pragma unroll
    for (int i = 0; i < 4; i++)
#pragma unroll
        for (int j = 0; j < 4; j++) Oacc[i][j] = 0.f;

    float m_i[4], l_i[4];
#pragma unroll
    for (int i = 0; i < 4; i++) { m_i[i] = -1e30f; l_i[i] = 0.f; }

    for (int jt = 0; jt <= qt; jt++) {
        __syncthreads();                // prior PV phase done (also covers sQ on jt=0)
        const int k0 = jt * 64;
#pragma unroll
        for (int it = 0; it < 4; it++) {
            int idx = t + it * 256;
            int r   = idx >> 4;
            int d4  = (idx & 15) * 4;
            size_t goff = base + (size_t)(k0 + r) * E_ + d4;
            float4 kv = *(const float4*)(Kt + goff);
            float4 vv = *(const float4*)(V  + goff);
            sK[r * AT_PAD + d4 + 0] = kv.x; sK[r * AT_PAD + d4 + 1] = kv.y;
            sK[r * AT_PAD + d4 + 2] = kv.z; sK[r * AT_PAD + d4 + 3] = kv.w;
            sV[r * AT_PAD + d4 + 0] = vv.x; sV[r * AT_PAD + d4 + 1] = vv.y;
            sV[r * AT_PAD + d4 + 2] = vv.z; sV[r * AT_PAD + d4 + 3] = vv.w;
        }
        __syncthreads();

        // --- scores: 4x4 micro-tile, Q[rows] . K[cols] ---
        float acc[4][4];
#pragma unroll
        for (int i = 0; i < 4; i++)
#pragma unroll
            for (int j = 0; j < 4; j++) acc[i][j] = 0.f;

        for (int d = 0; d < 64; d += 4) {
            float4 aq[4], ak[4];
#pragma unroll
            for (int i = 0; i < 4; i++)
                aq[i] = *(const float4*)&sQ[(ty * 4 + i) * AT_PAD + d];
#pragma unroll
            for (int j = 0; j < 4; j++)
                ak[j] = *(const float4*)&sK[(tx * 4 + j) * AT_PAD + d];
#pragma unroll
            for (int i = 0; i < 4; i++)
#pragma unroll
                for (int j = 0; j < 4; j++) {
                    acc[i][j] = fmaf(aq[i].x, ak[j].x, acc[i][j]);
                    acc[i][j] = fmaf(aq[i].y, ak[j].y, acc[i][j]);
                    acc[i][j] = fmaf(aq[i].z, ak[j].z, acc[i][j]);
                    acc[i][j] = fmaf(aq[i].w, ak[j].w, acc[i][j]);
                }
        }

        // scale + causal mask (only needed on the diagonal tile)
        const bool diag = (jt == qt);
#pragma unroll
        for (int i = 0; i < 4; i++)
#pragma unroll
            for (int j = 0; j < 4; j++) {
                float s = acc[i][j] * SCALE_;
                if (diag && (k0 + tx * 4 + j) > (q0 + ty * 4 + i)) s = -1e30f;
                acc[i][j] = s;
            }

        // --- online softmax per query row (width-16 shuffle reductions) ---
#pragma unroll
        for (int i = 0; i < 4; i++) {
            const int row = ty * 4 + i;
            float mx = fmaxf(fmaxf(acc[i][0], acc[i][1]),
                             fmaxf(acc[i][2], acc[i][3]));
#pragma unroll
            for (int off = 8; off >= 1; off >>= 1)
                mx = fmaxf(mx, __shfl_xor_sync(0xffffffffu, mx, off, 16));
            const float m_new = fmaxf(m_i[i], mx);
            float p[4], ls = 0.f;
#pragma unroll
            for (int j = 0; j < 4; j++) {
                p[j] = __expf(acc[i][j] - m_new);
                ls += p[j];
            }
#pragma unroll
            for (int off = 8; off >= 1; off >>= 1)
                ls += __shfl_xor_sync(0xffffffffu, ls, off, 16);
            const float alpha = __expf(m_i[i] - m_new);
            l_i[i] = l_i[i] * alpha + ls;
            m_i[i] = m_new;
#pragma unroll
            for (int j = 0; j < 4; j++) Oacc[i][j] *= alpha;
            float4 p4; p4.x = p[0]; p4.y = p[1]; p4.z = p[2]; p4.w = p[3];
            *(float4*)&sP[row * AT_PAD + tx * 4] = p4;
        }
        __syncthreads();

        // --- O += P @ V  (rows = queries, cols = d) ---
        for (int kk = 0; kk < 64; kk += 4) {
            float4 pv[4];
#pragma unroll
            for (int i = 0; i < 4; i++)
                pv[i] = *(const float4*)&sP[(ty * 4 + i) * AT_PAD + kk];
            float4 v0 = *(const float4*)&sV[(kk + 0) * AT_PAD + tx * 4];
            float4 v1 = *(const float4*)&sV[(kk + 1) * AT_PAD + tx * 4];
            float4 v2 = *(const float4*)&sV[(kk + 2) * AT_PAD + tx * 4];
            float4 v3 = *(const float4*)&sV[(kk + 3) * AT_PAD + tx * 4];
#pragma unroll
            for (int i = 0; i < 4; i++) {
                Oacc[i][0] = fmaf(pv[i].x, v0.x, Oacc[i][0]);
                Oacc[i][1] = fmaf(pv[i].x, v0.y, Oacc[i][1]);
                Oacc[i][2] = fmaf(pv[i].x, v0.z, Oacc[i][2]);
                Oacc[i][3] = fmaf(pv[i].x, v0.w, Oacc[i][3]);
                Oacc[i][0] = fmaf(pv[i].y, v1.x, Oacc[i][0]);
                Oacc[i][1] = fmaf(pv[i].y, v1.y, Oacc[i][1]);
                Oacc[i][2] = fmaf(pv[i].y, v1.z, Oacc[i][2]);
                Oacc[i][3] = fmaf(pv[i].y, v1.w, Oacc[i][3]);
                Oacc[i][0] = fmaf(pv[i].z, v2.x, Oacc[i][0]);
                Oacc[i][1] = fmaf(pv[i].z, v2.y, Oacc[i][1]);
                Oacc[i][2] = fmaf(pv[i].z, v2.z, Oacc[i][2]);
                Oacc[i][3] = fmaf(pv[i].z, v2.w, Oacc[i][3]);
                Oacc[i][0] = fmaf(pv[i].w, v3.x, Oacc[i][0]);
                Oacc[i][1] = fmaf(pv[i].w, v3.y, Oacc[i][1]);
                Oacc[i][2] = fmaf(pv[i].w, v3.z, Oacc[i][2]);
                Oacc[i][3] = fmaf(pv[i].w, v3.w, Oacc[i][3]);
            }
        }
    }

    // epilogue: normalize and store
#pragma unroll
    for (int i = 0; i < 4; i++) {
        const int row = ty * 4 + i;
        const float inv = 1.f / l_i[i];
        float4 o;
        o.x = Oacc[i][0] * inv; o.y = Oacc[i][1] * inv;
        o.z = Oacc[i][2] * inv; o.w = Oacc[i][3] * inv;
        *(float4*)(O + base + (size_t)(q0 + row) * E_ + tx * 4) = o;
    }
}

// ---------------------------------------------------------------------------
extern "C" void kernel_launch(void* const* d_in, const int* in_sizes, int n_in,
                              void* d_out, int out_size)
{
    const float* x  = (const float*)d_in[0];
    const float* Wq = (const float*)d_in[1];
    const float* bq = (const float*)d_in[2];
    const float* Wk = (const float*)d_in[3];
    const float* bk = (const float*)d_in[4];
    const float* Wv = (const float*)d_in[5];
    const float* bv = (const float*)d_in[6];
    const float* Wo = (const float*)d_in[7];
    const float* bo = (const float*)d_in[8];
    float* out = (float*)d_out;

    float *q_p, *k_p, *v_p, *a_p;
    cudaGetSymbolAddress((void**)&q_p, g_q);
    cudaGetSymbolAddress((void**)&k_p, g_k);
    cudaGetSymbolAddress((void**)&v_p, g_v);
    cudaGetSymbolAddress((void**)&a_p, g_attn);

    const size_t attn_smem = 4 * 64 * AT_PAD * sizeof(float); // ~69.6 KB
    cudaFuncSetAttribute(flash_attn,
                         cudaFuncAttributeMaxDynamicSharedMemorySize,
                         (int)attn_smem);

    dim3 gg(E_ / 128, M_ / 128);   // (16, 32)
    sgemm_bias<<<gg, 256>>>(x, Wq, bq, q_p, M_, E_, E_);
    sgemm_bias<<<gg, 256>>>(x, Wk, bk, k_p, M_, E_, E_);
    sgemm_bias<<<gg, 256>>>(x, Wv, bv, v_p, M_, E_, E_);

    dim3 ga(S_ / 64, B_ * H_);     // (32, 64)
    flash_attn<<<ga, 256, attn_smem>>>(q_p, k_p, v_p, a_p);

    sgemm_bias<<<gg, 256>>>(a_p, Wo, bo, out, M_, E_, E_);
}

// round 3
// speedup vs baseline: 1.8717x; 1.8717x over previous
#include <cuda_runtime.h>
#include <cuda_bf16.h>
#include <cstdint>
#include <math.h>

#define B_ 2
#define S_ 2048
#define E_ 2048
#define H_ 32
#define D_ 64
#define M_ (B_*S_)
#define SCALE_ 0.125f

// ---------------- scratch (static device allocations allowed) ----------------
static __device__ float g_q[(size_t)M_ * E_];
static __device__ float g_k[(size_t)M_ * E_];
static __device__ float g_v[(size_t)M_ * E_];
static __device__ float g_attn[(size_t)M_ * E_];

static __device__ __nv_bfloat16 g_xh[(size_t)M_ * E_];
static __device__ __nv_bfloat16 g_xl[(size_t)M_ * E_];
static __device__ __nv_bfloat16 g_ah[(size_t)M_ * E_];
static __device__ __nv_bfloat16 g_al[(size_t)M_ * E_];
static __device__ __nv_bfloat16 g_wqh[(size_t)E_ * E_];
static __device__ __nv_bfloat16 g_wql[(size_t)E_ * E_];
static __device__ __nv_bfloat16 g_wkh[(size_t)E_ * E_];
static __device__ __nv_bfloat16 g_wkl[(size_t)E_ * E_];
static __device__ __nv_bfloat16 g_wvh[(size_t)E_ * E_];
static __device__ __nv_bfloat16 g_wvl[(size_t)E_ * E_];
static __device__ __nv_bfloat16 g_woh[(size_t)E_ * E_];
static __device__ __nv_bfloat16 g_wol[(size_t)E_ * E_];

// ---------------- helpers ----------------
__device__ __forceinline__ uint32_t smem_u32(const void* p) {
    uint32_t a;
    asm("{ .reg .u64 t; cvta.to.shared.u64 t, %1; cvt.u32.u64 %0, t; }"
        : "=r"(a) : "l"(p));
    return a;
}

__device__ __forceinline__ void cp_async16(uint32_t saddr, const void* gaddr) {
    asm volatile("cp.async.cg.shared.global [%0], [%1], 16;\n"
                 :: "r"(saddr), "l"(gaddr));
}
#define CP_COMMIT() asm volatile("cp.async.commit_group;\n" ::: "memory")
#define CP_WAIT1()  asm volatile("cp.async.wait_group 1;\n" ::: "memory")

__device__ __forceinline__ void ldm_x4(uint32_t* r, uint32_t addr) {
    asm volatile("ldmatrix.sync.aligned.m8n8.x4.shared.b16 {%0,%1,%2,%3}, [%4];"
                 : "=r"(r[0]), "=r"(r[1]), "=r"(r[2]), "=r"(r[3]) : "r"(addr));
}

__device__ __forceinline__ void mma16816(float* d, const uint32_t* a,
                                         uint32_t b0, uint32_t b1) {
    asm volatile(
        "mma.sync.aligned.m16n8k16.row.col.f32.bf16.bf16.f32 "
        "{%0,%1,%2,%3}, {%4,%5,%6,%7}, {%8,%9}, {%0,%1,%2,%3};"
        : "+f"(d[0]), "+f"(d[1]), "+f"(d[2]), "+f"(d[3])
        : "r"(a[0]), "r"(a[1]), "r"(a[2]), "r"(a[3]), "r"(b0), "r"(b1));
}

// ---------------------------------------------------------------------------
// fp32 -> (bf16 hi, bf16 lo) split
// ---------------------------------------------------------------------------
__global__ void split_f32(const float* __restrict__ x,
                          __nv_bfloat16* __restrict__ hi,
                          __nv_bfloat16* __restrict__ lo, int n4)
{
    int i = blockIdx.x * blockDim.x + threadIdx.x;
    if (i >= n4) return;
    float4 v = ((const float4*)x)[i];
    __nv_bfloat16 h0 = __float2bfloat16(v.x);
    __nv_bfloat16 h1 = __float2bfloat16(v.y);
    __nv_bfloat16 h2 = __float2bfloat16(v.z);
    __nv_bfloat16 h3 = __float2bfloat16(v.w);
    __nv_bfloat16 l0 = __float2bfloat16(v.x - __bfloat162float(h0));
    __nv_bfloat16 l1 = __float2bfloat16(v.y - __bfloat162float(h1));
    __nv_bfloat16 l2 = __float2bfloat16(v.z - __bfloat162float(h2));
    __nv_bfloat16 l3 = __float2bfloat16(v.w - __bfloat162float(h3));
    __nv_bfloat162* hp = (__nv_bfloat162*)hi;
    __nv_bfloat162* lp = (__nv_bfloat162*)lo;
    hp[2*i]   = __nv_bfloat162(h0, h1);
    hp[2*i+1] = __nv_bfloat162(h2, h3);
    lp[2*i]   = __nv_bfloat162(l0, l1);
    lp[2*i+1] = __nv_bfloat162(l2, l3);
}

// ---------------------------------------------------------------------------
// Split-bf16 HMMA GEMM: C[4096,2048] = A @ B^T + bias
// CTA tile 128x128, BK=32, 8 warps (2Mx4N), warp tile 64x32, cp.async 2-stage.
// smem per stage: Ah(8K) Al(8K) Bh(8K) Bl(8K) = 32KB; 2 stages = 64KB.
// Swizzle: 16B chunk c of row r stored at chunk (c ^ ((r>>1)&3)).
// ---------------------------------------------------------------------------
#define GK 2048
#define NCH (GK / 32)   // 64 K-chunks
#define STG 32768

__device__ __forceinline__ void gemm_load_stage(
    const __nv_bfloat16* __restrict__ Ah, const __nv_bfloat16* __restrict__ Al,
    const __nv_bfloat16* __restrict__ Bh, const __nv_bfloat16* __restrict__ Bl,
    int m0, int n0, int k0, uint32_t sb, int t)
{
#pragma unroll
    for (int i = 0; i < 2; i++) {
        int idx = t + i * 256;          // 0..511
        int r = idx >> 2, c = idx & 3;
        uint32_t soff = (uint32_t)(r * 64 + (((c ^ ((r >> 1) & 3))) << 4));
        const size_t ga = (size_t)(m0 + r) * GK + k0 + c * 8;
        const size_t gb = (size_t)(n0 + r) * GK + k0 + c * 8;
        cp_async16(sb +             soff, Ah + ga);
        cp_async16(sb +  8192u +    soff, Al + ga);
        cp_async16(sb + 16384u +    soff, Bh + gb);
        cp_async16(sb + 24576u +    soff, Bl + gb);
    }
}

__global__ __launch_bounds__(256) void gemm_split_hmma(
    const __nv_bfloat16* __restrict__ Ah, const __nv_bfloat16* __restrict__ Al,
    const __nv_bfloat16* __restrict__ Bh, const __nv_bfloat16* __restrict__ Bl,
    const float* __restrict__ bias, float* __restrict__ C)
{
    extern __shared__ char smem[];
    const uint32_t sbase = smem_u32(smem);
    const int t = threadIdx.x;
    const int lane = t & 31, wid = t >> 5;
    const int warp_m = wid >> 2, warp_n = wid & 3;   // 2 x 4
    const int m0 = blockIdx.y * 128;
    const int n0 = blockIdx.x * 128;

    // per-thread ldmatrix row constants
    int a_row[4], b_row[2];
    uint32_t a_sw[4], b_sw[2];
#pragma unroll
    for (int mt = 0; mt < 4; mt++) {
        a_row[mt] = warp_m * 64 + mt * 16 + (lane & 15);
        a_sw[mt]  = (uint32_t)((a_row[mt] >> 1) & 3);
    }
#pragma unroll
    for (int pt = 0; pt < 2; pt++) {
        b_row[pt] = warp_n * 32 + pt * 16 + (lane & 7) + ((lane >> 4) & 1) * 8;
        b_sw[pt]  = (uint32_t)((b_row[pt] >> 1) & 3);
    }
    const uint32_t a_ch = (uint32_t)(lane >> 4);        // 0/1 -> k half
    const uint32_t b_ch = (uint32_t)((lane >> 3) & 1);  // 0/1 -> k half

    float acc[4][4][4];
#pragma unroll
    for (int i = 0; i < 4; i++)
#pragma unroll
        for (int j = 0; j < 4; j++)
#pragma unroll
            for (int q = 0; q < 4; q++) acc[i][j][q] = 0.f;

    gemm_load_stage(Ah, Al, Bh, Bl, m0, n0, 0,  sbase,        t); CP_COMMIT();
    gemm_load_stage(Ah, Al, Bh, Bl, m0, n0, 32, sbase + STG,  t); CP_COMMIT();

    for (int ch = 0; ch < NCH; ch++) {
        CP_WAIT1();
        __syncthreads();
        const uint32_t sb = sbase + (uint32_t)(ch & 1) * STG;

#pragma unroll
        for (int s = 0; s < 2; s++) {
            uint32_t Af[2][4][4];   // [hi/lo][mtile][4 regs]
            uint32_t Bf[2][2][4];   // [hi/lo][pair][4 regs]
#pragma unroll
            for (int mt = 0; mt < 4; mt++) {
                uint32_t c = (uint32_t)(s * 2) + a_ch;
                uint32_t off = (uint32_t)(a_row[mt] * 64) + ((c ^ a_sw[mt]) << 4);
                ldm_x4(Af[0][mt], sb + off);
                ldm_x4(Af[1][mt], sb + 8192u + off);
            }
#pragma unroll
            for (int pt = 0; pt < 2; pt++) {
                uint32_t c = (uint32_t)(s * 2) + b_ch;
                uint32_t off = (uint32_t)(b_row[pt] * 64) + ((c ^ b_sw[pt]) << 4);
                ldm_x4(Bf[0][pt], sb + 16384u + off);
                ldm_x4(Bf[1][pt], sb + 24576u + off);
            }
#pragma unroll
            for (int mt = 0; mt < 4; mt++)
#pragma unroll
                for (int nt = 0; nt < 4; nt++) {
                    const int pt = nt >> 1, hl = (nt & 1) * 2;
                    mma16816(acc[mt][nt], Af[0][mt], Bf[0][pt][hl], Bf[0][pt][hl+1]);
                    mma16816(acc[mt][nt], Af[0][mt], Bf[1][pt][hl], Bf[1][pt][hl+1]);
                    mma16816(acc[mt][nt], Af[1][mt], Bf[0][pt][hl], Bf[0][pt][hl+1]);
                }
        }
        __syncthreads();
        if (ch + 2 < NCH) {
            gemm_load_stage(Ah, Al, Bh, Bl, m0, n0, (ch + 2) * 32,
                            sbase + (uint32_t)(ch & 1) * STG, t);
        }
        CP_COMMIT();
    }

    // epilogue: acc thread mapping: c0,c1 -> (row lane/4, col 2*(lane%4)),
    // c2,c3 -> (row lane/4 + 8, same cols)
#pragma unroll
    for (int mt = 0; mt < 4; mt++) {
#pragma unroll
        for (int nt = 0; nt < 4; nt++) {
            const int r0 = m0 + warp_m * 64 + mt * 16 + (lane >> 2);
            const int cc = n0 + warp_n * 32 + nt * 8 + (lane & 3) * 2;
            const float bx = bias[cc], by = bias[cc + 1];
            float2 v0 = make_float2(acc[mt][nt][0] + bx, acc[mt][nt][1] + by);
            float2 v1 = make_float2(acc[mt][nt][2] + bx, acc[mt][nt][3] + by);
            *(float2*)(C + (size_t)r0 * GK + cc)       = v0;
            *(float2*)(C + (size_t)(r0 + 8) * GK + cc) = v1;
        }
    }
}

// ---------------------------------------------------------------------------
// Flash attention (causal), fp32 — unchanged (validated round 1).
// ---------------------------------------------------------------------------
#define AT_PAD 68

__global__ __launch_bounds__(256) void flash_attn(
    const float* __restrict__ Q, const float* __restrict__ Kt,
    const float* __restrict__ V, float* __restrict__ O)
{
    extern __shared__ float fsmem[];
    float* sQ = fsmem;
    float* sK = sQ + 64 * AT_PAD;
    float* sV = sK + 64 * AT_PAD;
    float* sP = sV + 64 * AT_PAD;

    const int t  = threadIdx.x;
    const int tx = t & 15;
    const int ty = t >> 4;
    const int qt = blockIdx.x;
    const int bh = blockIdx.y;
    const int b  = bh / H_;
    const int h  = bh % H_;
    const int q0 = qt * 64;

    const size_t base = ((size_t)b * S_) * E_ + (size_t)h * D_;

#pragma unroll
    for (int it = 0; it < 4; it++) {
        int idx = t + it * 256;
        int r   = idx >> 4;
        int d4  = (idx & 15) * 4;
        float4 qv = *(const float4*)(Q + base + (size_t)(q0 + r) * E_ + d4);
        sQ[r * AT_PAD + d4 + 0] = qv.x;
        sQ[r * AT_PAD + d4 + 1] = qv.y;
        sQ[r * AT_PAD + d4 + 2] = qv.z;
        sQ[r * AT_PAD + d4 + 3] = qv.w;
    }

    float Oacc[4][4];
#pragma unroll
    for (int i = 0; i < 4; i++)
#pragma unroll
        for (int j = 0; j < 4; j++) Oacc[i][j] = 0.f;

    float m_i[4], l_i[4];
#pragma unroll
    for (int i = 0; i < 4; i++) { m_i[i] = -1e30f; l_i[i] = 0.f; }

    for (int jt = 0; jt <= qt; jt++) {
        __syncthreads();
        const int k0 = jt * 64;
#pragma unroll
        for (int it = 0; it < 4; it++) {
            int idx = t + it * 256;
            int r   = idx >> 4;
            int d4  = (idx & 15) * 4;
            size_t goff = base + (size_t)(k0 + r) * E_ + d4;
            float4 kv = *(const float4*)(Kt + goff);
            float4 vv = *(const float4*)(V  + goff);
            sK[r * AT_PAD + d4 + 0] = kv.x; sK[r * AT_PAD + d4 + 1] = kv.y;
            sK[r * AT_PAD + d4 + 2] = kv.z; sK[r * AT_PAD + d4 + 3] = kv.w;
            sV[r * AT_PAD + d4 + 0] = vv.x; sV[r * AT_PAD + d4 + 1] = vv.y;
            sV[r * AT_PAD + d4 + 2] = vv.z; sV[r * AT_PAD + d4 + 3] = vv.w;
        }
        __syncthreads();

        float acc[4][4];
#pragma unroll
        for (int i = 0; i < 4; i++)
#pragma unroll
            for (int j = 0; j < 4; j++) acc[i][j] = 0.f;

        for (int d = 0; d < 64; d += 4) {
            float4 aq[4], ak[4];
#pragma unroll
            for (int i = 0; i < 4; i++)
                aq[i] = *(const float4*)&sQ[(ty * 4 + i) * AT_PAD + d];
#pragma unroll
            for (int j = 0; j < 4; j++)
                ak[j] = *(const float4*)&sK[(tx * 4 + j) * AT_PAD + d];
#pragma unroll
            for (int i = 0; i < 4; i++)
#pragma unroll
                for (int j = 0; j < 4; j++) {
                    acc[i][j] = fmaf(aq[i].x, ak[j].x, acc[i][j]);
                    acc[i][j] = fmaf(aq[i].y, ak[j].y, acc[i][j]);
                    acc[i][j] = fmaf(aq[i].z, ak[j].z, acc[i][j]);
                    acc[i][j] = fmaf(aq[i].w, ak[j].w, acc[i][j]);
                }
        }

        const bool diag = (jt == qt);
#pragma unroll
        for (int i = 0; i < 4; i++)
#pragma unroll
            for (int j = 0; j < 4; j++) {
                float s = acc[i][j] * SCALE_;
                if (diag && (k0 + tx * 4 + j) > (q0 + ty * 4 + i)) s = -1e30f;
                acc[i][j] = s;
            }

#pragma unroll
        for (int i = 0; i < 4; i++) {
            const int row = ty * 4 + i;
            float mx = fmaxf(fmaxf(acc[i][0], acc[i][1]),
                             fmaxf(acc[i][2], acc[i][3]));
#pragma unroll
            for (int off = 8; off >= 1; off >>= 1)
                mx = fmaxf(mx, __shfl_xor_sync(0xffffffffu, mx, off, 16));
            const float m_new = fmaxf(m_i[i], mx);
            float p[4], ls = 0.f;
#pragma unroll
            for (int j = 0; j < 4; j++) {
                p[j] = __expf(acc[i][j] - m_new);
                ls += p[j];
            }
#pragma unroll
            for (int off = 8; off >= 1; off >>= 1)
                ls += __shfl_xor_sync(0xffffffffu, ls, off, 16);
            const float alpha = __expf(m_i[i] - m_new);
            l_i[i] = l_i[i] * alpha + ls;
            m_i[i] = m_new;
#pragma unroll
            for (int j = 0; j < 4; j++) Oacc[i][j] *= alpha;
            float4 p4; p4.x = p[0]; p4.y = p[1]; p4.z = p[2]; p4.w = p[3];
            *(float4*)&sP[row * AT_PAD + tx * 4] = p4;
        }
        __syncthreads();

        for (int kk = 0; kk < 64; kk += 4) {
            float4 pv[4];
#pragma unroll
            for (int i = 0; i < 4; i++)
                pv[i] = *(const float4*)&sP[(ty * 4 + i) * AT_PAD + kk];
            float4 v0 = *(const float4*)&sV[(kk + 0) * AT_PAD + tx * 4];
            float4 v1 = *(const float4*)&sV[(kk + 1) * AT_PAD + tx * 4];
            float4 v2 = *(const float4*)&sV[(kk + 2) * AT_PAD + tx * 4];
            float4 v3 = *(const float4*)&sV[(kk + 3) * AT_PAD + tx * 4];
#pragma unroll
            for (int i = 0; i < 4; i++) {
                Oacc[i][0] = fmaf(pv[i].x, v0.x, Oacc[i][0]);
                Oacc[i][1] = fmaf(pv[i].x, v0.y, Oacc[i][1]);
                Oacc[i][2] = fmaf(pv[i].x, v0.z, Oacc[i][2]);
                Oacc[i][3] = fmaf(pv[i].x, v0.w, Oacc[i][3]);
                Oacc[i][0] = fmaf(pv[i].y, v1.x, Oacc[i][0]);
                Oacc[i][1] = fmaf(pv[i].y, v1.y, Oacc[i][1]);
                Oacc[i][2] = fmaf(pv[i].y, v1.z, Oacc[i][2]);
                Oacc[i][3] = fmaf(pv[i].y, v1.w, Oacc[i][3]);
                Oacc[i][0] = fmaf(pv[i].z, v2.x, Oacc[i][0]);
                Oacc[i][1] = fmaf(pv[i].z, v2.y, Oacc[i][1]);
                Oacc[i][2] = fmaf(pv[i].z, v2.z, Oacc[i][2]);
                Oacc[i][3] = fmaf(pv[i].z, v2.w, Oacc[i][3]);
                Oacc[i][0] = fmaf(pv[i].w, v3.x, Oacc[i][0]);
                Oacc[i][1] = fmaf(pv[i].w, v3.y, Oacc[i][1]);
                Oacc[i][2] = fmaf(pv[i].w, v3.z, Oacc[i][2]);
                Oacc[i][3] = fmaf(pv[i].w, v3.w, Oacc[i][3]);
            }
        }
    }

#pragma unroll
    for (int i = 0; i < 4; i++) {
        const int row = ty * 4 + i;
        const float inv = 1.f / l_i[i];
        float4 o;
        o.x = Oacc[i][0] * inv; o.y = Oacc[i][1] * inv;
        o.z = Oacc[i][2] * inv; o.w = Oacc[i][3] * inv;
        *(float4*)(O + base + (size_t)(q0 + row) * E_ + tx * 4) = o;
    }
}

// ---------------------------------------------------------------------------
extern "C" void kernel_launch(void* const* d_in, const int* in_sizes, int n_in,
                              void* d_out, int out_size)
{
    const float* x  = (const float*)d_in[0];
    const float* Wq = (const float*)d_in[1];
    const float* bq = (const float*)d_in[2];
    const float* Wk = (const float*)d_in[3];
    const float* bk = (const float*)d_in[4];
    const float* Wv = (const float*)d_in[5];
    const float* bv = (const float*)d_in[6];
    const float* Wo = (const float*)d_in[7];
    const float* bo = (const float*)d_in[8];
    float* out = (float*)d_out;

    float *q_p, *k_p, *v_p, *a_p;
    cudaGetSymbolAddress((void**)&q_p, g_q);
    cudaGetSymbolAddress((void**)&k_p, g_k);
    cudaGetSymbolAddress((void**)&v_p, g_v);
    cudaGetSymbolAddress((void**)&a_p, g_attn);

    __nv_bfloat16 *xh, *xl, *ah, *al;
    __nv_bfloat16 *wqh, *wql, *wkh, *wkl, *wvh, *wvl, *woh, *wol;
    cudaGetSymbolAddress((void**)&xh, g_xh);
    cudaGetSymbolAddress((void**)&xl, g_xl);
    cudaGetSymbolAddress((void**)&ah, g_ah);
    cudaGetSymbolAddress((void**)&al, g_al);
    cudaGetSymbolAddress((void**)&wqh, g_wqh);
    cudaGetSymbolAddress((void**)&wql, g_wql);
    cudaGetSymbolAddress((void**)&wkh, g_wkh);
    cudaGetSymbolAddress((void**)&wkl, g_wkl);
    cudaGetSymbolAddress((void**)&wvh, g_wvh);
    cudaGetSymbolAddress((void**)&wvl, g_wvl);
    cudaGetSymbolAddress((void**)&woh, g_woh);
    cudaGetSymbolAddress((void**)&wol, g_wol);

    cudaFuncSetAttribute(gemm_split_hmma,
                         cudaFuncAttributeMaxDynamicSharedMemorySize, 2 * STG);
    const size_t attn_smem = 4 * 64 * AT_PAD * sizeof(float);
    cudaFuncSetAttribute(flash_attn,
                         cudaFuncAttributeMaxDynamicSharedMemorySize, (int)attn_smem);

    const int n4x = (M_ * E_) / 4;
    const int n4w = (E_ * E_) / 4;
    split_f32<<<(n4x + 255) / 256, 256>>>(x,  xh,  xl,  n4x);
    split_f32<<<(n4w + 255) / 256, 256>>>(Wq, wqh, wql, n4w);
    split_f32<<<(n4w + 255) / 256, 256>>>(Wk, wkh, wkl, n4w);
    split_f32<<<(n4w + 255) / 256, 256>>>(Wv, wvh, wvl, n4w);
    split_f32<<<(n4w + 255) / 256, 256>>>(Wo, woh, wol, n4w);

    dim3 gg(E_ / 128, M_ / 128);   // (16, 32)
    gemm_split_hmma<<<gg, 256, 2 * STG>>>(xh, xl, wqh, wql, bq, q_p);
    gemm_split_hmma<<<gg, 256, 2 * STG>>>(xh, xl, wkh, wkl, bk, k_p);
    gemm_split_hmma<<<gg, 256, 2 * STG>>>(xh, xl, wvh, wvl, bv, v_p);

    dim3 ga(S_ / 64, B_ * H_);     // (32, 64)
    flash_attn<<<ga, 256, attn_smem>>>(q_p, k_p, v_p, a_p);

    split_f32<<<(n4x + 255) / 256, 256>>>(a_p, ah, al, n4x);
    gemm_split_hmma<<<gg, 256, 2 * STG>>>(ah, al, woh, wol, bo, out);
}

// round 4
// speedup vs baseline: 3.5960x; 1.9213x over previous
#include <cuda_runtime.h>
#include <cuda_bf16.h>
#include <cstdint>
#include <math.h>

#define B_ 2
#define S_ 2048
#define E_ 2048
#define H_ 32
#define D_ 64
#define M_ (B_*S_)
#define SCALE_ 0.125f

// ---------------- scratch (static device allocations allowed) ----------------
static __device__ __nv_bfloat16 g_xh[(size_t)M_ * E_];
static __device__ __nv_bfloat16 g_xl[(size_t)M_ * E_];
static __device__ __nv_bfloat16 g_qh[(size_t)M_ * E_];
static __device__ __nv_bfloat16 g_ql[(size_t)M_ * E_];
static __device__ __nv_bfloat16 g_kh[(size_t)M_ * E_];
static __device__ __nv_bfloat16 g_kl[(size_t)M_ * E_];
static __device__ __nv_bfloat16 g_vh[(size_t)M_ * E_];
static __device__ __nv_bfloat16 g_vl[(size_t)M_ * E_];
static __device__ __nv_bfloat16 g_ah[(size_t)M_ * E_];
static __device__ __nv_bfloat16 g_al[(size_t)M_ * E_];
static __device__ __nv_bfloat16 g_wqh[(size_t)E_ * E_];
static __device__ __nv_bfloat16 g_wql[(size_t)E_ * E_];
static __device__ __nv_bfloat16 g_wkh[(size_t)E_ * E_];
static __device__ __nv_bfloat16 g_wkl[(size_t)E_ * E_];
static __device__ __nv_bfloat16 g_wvh[(size_t)E_ * E_];
static __device__ __nv_bfloat16 g_wvl[(size_t)E_ * E_];
static __device__ __nv_bfloat16 g_woh[(size_t)E_ * E_];
static __device__ __nv_bfloat16 g_wol[(size_t)E_ * E_];

// ---------------- helpers ----------------
__device__ __forceinline__ uint32_t smem_u32(const void* p) {
    uint32_t a;
    asm("{ .reg .u64 t; cvta.to.shared.u64 t, %1; cvt.u32.u64 %0, t; }"
        : "=r"(a) : "l"(p));
    return a;
}
__device__ __forceinline__ void cp_async16(uint32_t saddr, const void* gaddr) {
    asm volatile("cp.async.cg.shared.global [%0], [%1], 16;\n"
                 :: "r"(saddr), "l"(gaddr));
}
#define CP_COMMIT() asm volatile("cp.async.commit_group;\n" ::: "memory")
#define CP_WAIT1()  asm volatile("cp.async.wait_group 1;\n" ::: "memory")

__device__ __forceinline__ void ldm_x4(uint32_t* r, uint32_t addr) {
    asm volatile("ldmatrix.sync.aligned.m8n8.x4.shared.b16 {%0,%1,%2,%3}, [%4];"
                 : "=r"(r[0]), "=r"(r[1]), "=r"(r[2]), "=r"(r[3]) : "r"(addr));
}
__device__ __forceinline__ void ldm_x4t(uint32_t* r, uint32_t addr) {
    asm volatile("ldmatrix.sync.aligned.m8n8.x4.trans.shared.b16 {%0,%1,%2,%3}, [%4];"
                 : "=r"(r[0]), "=r"(r[1]), "=r"(r[2]), "=r"(r[3]) : "r"(addr));
}
__device__ __forceinline__ void mma16816(float* d, const uint32_t* a,
                                         uint32_t b0, uint32_t b1) {
    asm volatile(
        "mma.sync.aligned.m16n8k16.row.col.f32.bf16.bf16.f32 "
        "{%0,%1,%2,%3}, {%4,%5,%6,%7}, {%8,%9}, {%0,%1,%2,%3};"
        : "+f"(d[0]), "+f"(d[1]), "+f"(d[2]), "+f"(d[3])
        : "r"(a[0]), "r"(a[1]), "r"(a[2]), "r"(a[3]), "r"(b0), "r"(b1));
}
__device__ __forceinline__ uint32_t packbf(float lo, float hi) {
    uint32_t d;
    asm("cvt.rn.bf16x2.f32 %0, %1, %2;" : "=r"(d) : "f"(hi), "f"(lo));
    return d;
}
__device__ __forceinline__ float bf_lo(uint32_t u) { return __uint_as_float(u << 16); }
__device__ __forceinline__ float bf_hi(uint32_t u) { return __uint_as_float(u & 0xffff0000u); }
__device__ __forceinline__ float ex2(float x) {
    float y; asm("ex2.approx.f32 %0, %1;" : "=f"(y) : "f"(x)); return y;
}

// ---------------------------------------------------------------------------
// fp32 -> (bf16 hi, bf16 lo) split
// ---------------------------------------------------------------------------
__global__ void split_f32(const float* __restrict__ x,
                          __nv_bfloat16* __restrict__ hi,
                          __nv_bfloat16* __restrict__ lo, int n4)
{
    int i = blockIdx.x * blockDim.x + threadIdx.x;
    if (i >= n4) return;
    float4 v = ((const float4*)x)[i];
    uint32_t h0 = packbf(v.x, v.y);
    uint32_t h1 = packbf(v.z, v.w);
    uint32_t l0 = packbf(v.x - bf_lo(h0), v.y - bf_hi(h0));
    uint32_t l1 = packbf(v.z - bf_lo(h1), v.w - bf_hi(h1));
    ((uint2*)hi)[i] = make_uint2(h0, h1);
    ((uint2*)lo)[i] = make_uint2(l0, l1);
}

// ---------------------------------------------------------------------------
// Split-bf16 HMMA GEMM: C = A @ B^T + bias.
// CTA 128x128, BK=32, 8 warps (2Mx4N), warp tile 64x32, cp.async 2-stage.
// SPLIT=false -> fp32 C; SPLIT=true -> bf16 (hi, lo) pair outputs.
// ---------------------------------------------------------------------------
#define GK 2048
#define NCH (GK / 32)
#define STG 32768

__device__ __forceinline__ void gemm_load_stage(
    const __nv_bfloat16* __restrict__ Ah, const __nv_bfloat16* __restrict__ Al,
    const __nv_bfloat16* __restrict__ Bh, const __nv_bfloat16* __restrict__ Bl,
    int m0, int n0, int k0, uint32_t sb, int t)
{
#pragma unroll
    for (int i = 0; i < 2; i++) {
        int idx = t + i * 256;
        int r = idx >> 2, c = idx & 3;
        uint32_t soff = (uint32_t)(r * 64 + (((c ^ ((r >> 1) & 3))) << 4));
        const size_t ga = (size_t)(m0 + r) * GK + k0 + c * 8;
        const size_t gb = (size_t)(n0 + r) * GK + k0 + c * 8;
        cp_async16(sb +          soff, Ah + ga);
        cp_async16(sb +  8192u + soff, Al + ga);
        cp_async16(sb + 16384u + soff, Bh + gb);
        cp_async16(sb + 24576u + soff, Bl + gb);
    }
}

template<bool SPLIT>
__global__ __launch_bounds__(256) void gemm_split_hmma(
    const __nv_bfloat16* __restrict__ Ah, const __nv_bfloat16* __restrict__ Al,
    const __nv_bfloat16* __restrict__ Bh, const __nv_bfloat16* __restrict__ Bl,
    const float* __restrict__ bias, float* __restrict__ C,
    __nv_bfloat16* __restrict__ Ch, __nv_bfloat16* __restrict__ Cl)
{
    extern __shared__ char smem[];
    const uint32_t sbase = smem_u32(smem);
    const int t = threadIdx.x;
    const int lane = t & 31, wid = t >> 5;
    const int warp_m = wid >> 2, warp_n = wid & 3;
    const int m0 = blockIdx.y * 128;
    const int n0 = blockIdx.x * 128;

    int a_row[4], b_row[2];
    uint32_t a_sw[4], b_sw[2];
#pragma unroll
    for (int mt = 0; mt < 4; mt++) {
        a_row[mt] = warp_m * 64 + mt * 16 + (lane & 15);
        a_sw[mt]  = (uint32_t)((a_row[mt] >> 1) & 3);
    }
#pragma unroll
    for (int pt = 0; pt < 2; pt++) {
        b_row[pt] = warp_n * 32 + pt * 16 + (lane & 7) + ((lane >> 4) & 1) * 8;
        b_sw[pt]  = (uint32_t)((b_row[pt] >> 1) & 3);
    }
    const uint32_t a_ch = (uint32_t)(lane >> 4);
    const uint32_t b_ch = (uint32_t)((lane >> 3) & 1);

    float acc[4][4][4];
#pragma unroll
    for (int i = 0; i < 4; i++)
#pragma unroll
        for (int j = 0; j < 4; j++)
#pragma unroll
            for (int q = 0; q < 4; q++) acc[i][j][q] = 0.f;

    gemm_load_stage(Ah, Al, Bh, Bl, m0, n0, 0,  sbase,       t); CP_COMMIT();
    gemm_load_stage(Ah, Al, Bh, Bl, m0, n0, 32, sbase + STG, t); CP_COMMIT();

    for (int ch = 0; ch < NCH; ch++) {
        CP_WAIT1();
        __syncthreads();
        const uint32_t sb = sbase + (uint32_t)(ch & 1) * STG;

#pragma unroll
        for (int s = 0; s < 2; s++) {
            uint32_t Af[2][4][4];
            uint32_t Bf[2][2][4];
#pragma unroll
            for (int mt = 0; mt < 4; mt++) {
                uint32_t c = (uint32_t)(s * 2) + a_ch;
                uint32_t off = (uint32_t)(a_row[mt] * 64) + ((c ^ a_sw[mt]) << 4);
                ldm_x4(Af[0][mt], sb + off);
                ldm_x4(Af[1][mt], sb + 8192u + off);
            }
#pragma unroll
            for (int pt = 0; pt < 2; pt++) {
                uint32_t c = (uint32_t)(s * 2) + b_ch;
                uint32_t off = (uint32_t)(b_row[pt] * 64) + ((c ^ b_sw[pt]) << 4);
                ldm_x4(Bf[0][pt], sb + 16384u + off);
                ldm_x4(Bf[1][pt], sb + 24576u + off);
            }
#pragma unroll
            for (int mt = 0; mt < 4; mt++)
#pragma unroll
                for (int nt = 0; nt < 4; nt++) {
                    const int pt = nt >> 1, hl = (nt & 1) * 2;
                    mma16816(acc[mt][nt], Af[0][mt], Bf[0][pt][hl], Bf[0][pt][hl+1]);
                    mma16816(acc[mt][nt], Af[0][mt], Bf[1][pt][hl], Bf[1][pt][hl+1]);
                    mma16816(acc[mt][nt], Af[1][mt], Bf[0][pt][hl], Bf[0][pt][hl+1]);
                }
        }
        __syncthreads();
        if (ch + 2 < NCH) {
            gemm_load_stage(Ah, Al, Bh, Bl, m0, n0, (ch + 2) * 32,
                            sbase + (uint32_t)(ch & 1) * STG, t);
        }
        CP_COMMIT();
    }

#pragma unroll
    for (int mt = 0; mt < 4; mt++) {
#pragma unroll
        for (int nt = 0; nt < 4; nt++) {
            const int r0 = m0 + warp_m * 64 + mt * 16 + (lane >> 2);
            const int cc = n0 + warp_n * 32 + nt * 8 + (lane & 3) * 2;
            const float bx = bias[cc], by = bias[cc + 1];
            float v0 = acc[mt][nt][0] + bx, v1 = acc[mt][nt][1] + by;
            float v2 = acc[mt][nt][2] + bx, v3 = acc[mt][nt][3] + by;
            if (!SPLIT) {
                *(float2*)(C + (size_t)r0 * GK + cc)       = make_float2(v0, v1);
                *(float2*)(C + (size_t)(r0 + 8) * GK + cc) = make_float2(v2, v3);
            } else {
                uint32_t h0 = packbf(v0, v1);
                uint32_t l0 = packbf(v0 - bf_lo(h0), v1 - bf_hi(h0));
                uint32_t h1 = packbf(v2, v3);
                uint32_t l1 = packbf(v2 - bf_lo(h1), v3 - bf_hi(h1));
                *(uint32_t*)(Ch + (size_t)r0 * GK + cc)       = h0;
                *(uint32_t*)(Cl + (size_t)r0 * GK + cc)       = l0;
                *(uint32_t*)(Ch + (size_t)(r0 + 8) * GK + cc) = h1;
                *(uint32_t*)(Cl + (size_t)(r0 + 8) * GK + cc) = l1;
            }
        }
    }
}

// ---------------------------------------------------------------------------
// Flash attention (causal) on HMMA, split-bf16.
// CTA: 256 queries x one (b,h). 8 warps x 32 query rows. KT=64 keys/iter,
// double-buffered cp.async K/V. Scores/P in registers; online softmax.
// Writes output as (hi, lo) bf16 for the final GEMM.
// ---------------------------------------------------------------------------
#define FQT 256
#define FKT 64
// smem: Qh 32K | Ql 32K | 2 stages x (Kh 8K, Kl 8K, Vh 8K, Vl 8K)
#define FA_SMEM 131072

__global__ __launch_bounds__(256) void flash_hmma(
    const __nv_bfloat16* __restrict__ Qh, const __nv_bfloat16* __restrict__ Ql,
    const __nv_bfloat16* __restrict__ Kh, const __nv_bfloat16* __restrict__ Kl,
    const __nv_bfloat16* __restrict__ Vh, const __nv_bfloat16* __restrict__ Vl,
    __nv_bfloat16* __restrict__ Oh, __nv_bfloat16* __restrict__ Ol)
{
    extern __shared__ char smem[];
    const uint32_t sb = smem_u32(smem);
    const int t = threadIdx.x, lane = t & 31, wid = t >> 5;
    const int qt = blockIdx.x, bh = blockIdx.y;
    const int b = bh >> 5, h = bh & 31;
    const int q0 = qt * FQT;
    const size_t qbase = ((size_t)b * S_ + q0) * E_ + h * D_;
    const size_t kbase = ((size_t)b * S_) * E_ + h * D_;

    const uint32_t oQh = 0, oQl = 32768, oKV = 65536;

    // Q tile load (both hi/lo), swizzled rows of 128B
#pragma unroll
    for (int i = 0; i < 8; i++) {
        int idx = t + i * 256, r = idx >> 3, c = idx & 7;
        uint32_t so = (uint32_t)(r * 128 + (((c ^ (r & 7))) << 4));
        size_t g = qbase + (size_t)r * E_ + c * 8;
        cp_async16(sb + oQh + so, Qh + g);
        cp_async16(sb + oQl + so, Ql + g);
    }
    const int jmax = 4 * (qt + 1);
    // KV tile 0 -> stage 0
#pragma unroll
    for (int i = 0; i < 2; i++) {
        int idx = t + i * 256, r = idx >> 3, c = idx & 7;
        uint32_t so = (uint32_t)(r * 128 + (((c ^ (r & 7))) << 4));
        size_t g = kbase + (size_t)r * E_ + c * 8;
        cp_async16(sb + oKV +          so, Kh + g);
        cp_async16(sb + oKV +  8192u + so, Kl + g);
        cp_async16(sb + oKV + 16384u + so, Vh + g);
        cp_async16(sb + oKV + 24576u + so, Vl + g);
    }
    CP_COMMIT();

    float Oacc[2][8][4];
#pragma unroll
    for (int i = 0; i < 2; i++)
#pragma unroll
        for (int j = 0; j < 8; j++)
#pragma unroll
            for (int q = 0; q < 4; q++) Oacc[i][j][q] = 0.f;
    float m_i[2][2] = {{-1e30f, -1e30f}, {-1e30f, -1e30f}};
    float l_i[2][2] = {{0.f, 0.f}, {0.f, 0.f}};
    const float CEXP = SCALE_ * 1.4426950408889634f;

    for (int jt = 0; jt < jmax; jt++) {
        const int k0 = jt * FKT;
        __syncthreads();                 // prior tile's reads of the alt stage done
        if (jt + 1 < jmax) {
            uint32_t st = oKV + (uint32_t)((jt + 1) & 1) * 32768u;
#pragma unroll
            for (int i = 0; i < 2; i++) {
                int idx = t + i * 256, r = idx >> 3, c = idx & 7;
                uint32_t so = (uint32_t)(r * 128 + (((c ^ (r & 7))) << 4));
                size_t g = kbase + (size_t)(k0 + FKT + r) * E_ + c * 8;
                cp_async16(sb + st +          so, Kh + g);
                cp_async16(sb + st +  8192u + so, Kl + g);
                cp_async16(sb + st + 16384u + so, Vh + g);
                cp_async16(sb + st + 24576u + so, Vl + g);
            }
        }
        CP_COMMIT();
        CP_WAIT1();
        __syncthreads();
        const uint32_t sKh = sb + oKV + (uint32_t)(jt & 1) * 32768u;
        const uint32_t sKl = sKh + 8192u;
        const uint32_t sVh = sKh + 16384u;
        const uint32_t sVl = sKh + 24576u;

        // ---- S = Q K^T (split, fp32 acc) ----
        float sacc[2][8][4];
#pragma unroll
        for (int i = 0; i < 2; i++)
#pragma unroll
            for (int j = 0; j < 8; j++)
#pragma unroll
                for (int q = 0; q < 4; q++) sacc[i][j][q] = 0.f;

#pragma unroll
        for (int kc = 0; kc < 4; kc++) {
            uint32_t aqh[2][4], aql[2][4];
#pragma unroll
            for (int mt = 0; mt < 2; mt++) {
                int row = wid * 32 + mt * 16 + (lane & 15);
                uint32_t ch = (uint32_t)(2 * kc + (lane >> 4));
                uint32_t off = (uint32_t)(row * 128) + ((ch ^ (uint32_t)(row & 7)) << 4);
                ldm_x4(aqh[mt], sb + oQh + off);
                ldm_x4(aql[mt], sb + oQl + off);
            }
#pragma unroll
            for (int np = 0; np < 4; np++) {
                int row = np * 16 + (lane & 7) + ((lane >> 4) & 1) * 8;
                uint32_t ch = (uint32_t)(2 * kc + ((lane >> 3) & 1));
                uint32_t off = (uint32_t)(row * 128) + ((ch ^ (uint32_t)(row & 7)) << 4);
                uint32_t bkh[4], bkl[4];
                ldm_x4(bkh, sKh + off);
                ldm_x4(bkl, sKl + off);
#pragma unroll
                for (int nt2 = 0; nt2 < 2; nt2++) {
                    const int snt = np * 2 + nt2;
#pragma unroll
                    for (int mt = 0; mt < 2; mt++) {
                        mma16816(sacc[mt][snt], aqh[mt], bkh[nt2*2], bkh[nt2*2+1]);
                        mma16816(sacc[mt][snt], aqh[mt], bkl[nt2*2], bkl[nt2*2+1]);
                        mma16816(sacc[mt][snt], aql[mt], bkh[nt2*2], bkh[nt2*2+1]);
                    }
                }
            }
        }

        // ---- causal mask (only tiles straddling the diagonal) ----
        if (k0 + FKT - 1 > q0) {
#pragma unroll
            for (int mt = 0; mt < 2; mt++)
#pragma unroll
                for (int nt = 0; nt < 8; nt++)
#pragma unroll
                    for (int e = 0; e < 4; e++) {
                        int qrow = q0 + wid * 32 + mt * 16 + (lane >> 2) + (e >> 1) * 8;
                        int kcol = k0 + nt * 8 + (lane & 3) * 2 + (e & 1);
                        if (kcol > qrow) sacc[mt][nt][e] = -1e30f;
                    }
        }

        // ---- online softmax (rows shared by 4 lanes; shuffle reductions) ----
#pragma unroll
        for (int mt = 0; mt < 2; mt++)
#pragma unroll
            for (int rr = 0; rr < 2; rr++) {
                float mx = -1e30f;
#pragma unroll
                for (int nt = 0; nt < 8; nt++)
                    mx = fmaxf(mx, fmaxf(sacc[mt][nt][rr*2], sacc[mt][nt][rr*2+1]));
                mx = fmaxf(mx, __shfl_xor_sync(0xffffffffu, mx, 1));
                mx = fmaxf(mx, __shfl_xor_sync(0xffffffffu, mx, 2));
                const float m_new = fmaxf(m_i[mt][rr], mx);
                const float mC = m_new * CEXP;
                const float alpha = ex2(m_i[mt][rr] * CEXP - mC);
                float rs = 0.f;
#pragma unroll
                for (int nt = 0; nt < 8; nt++) {
                    float p0 = ex2(sacc[mt][nt][rr*2]   * CEXP - mC);
                    float p1 = ex2(sacc[mt][nt][rr*2+1] * CEXP - mC);
                    sacc[mt][nt][rr*2] = p0; sacc[mt][nt][rr*2+1] = p1;
                    rs += p0 + p1;
                }
                rs += __shfl_xor_sync(0xffffffffu, rs, 1);
                rs += __shfl_xor_sync(0xffffffffu, rs, 2);
                l_i[mt][rr] = l_i[mt][rr] * alpha + rs;
                m_i[mt][rr] = m_new;
#pragma unroll
                for (int nd = 0; nd < 8; nd++) {
                    Oacc[mt][nd][rr*2]   *= alpha;
                    Oacc[mt][nd][rr*2+1] *= alpha;
                }
            }

        // ---- O += P V (P split into hi/lo; V fragments via ldmatrix.trans) ----
#pragma unroll
        for (int kc = 0; kc < 4; kc++) {
            uint32_t ph[2][4], pl[2][4];
#pragma unroll
            for (int mt = 0; mt < 2; mt++) {
                float p00 = sacc[mt][2*kc][0],   p01 = sacc[mt][2*kc][1];
                float p10 = sacc[mt][2*kc][2],   p11 = sacc[mt][2*kc][3];
                float p20 = sacc[mt][2*kc+1][0], p21 = sacc[mt][2*kc+1][1];
                float p30 = sacc[mt][2*kc+1][2], p31 = sacc[mt][2*kc+1][3];
                ph[mt][0] = packbf(p00, p01);
                ph[mt][1] = packbf(p10, p11);
                ph[mt][2] = packbf(p20, p21);
                ph[mt][3] = packbf(p30, p31);
                pl[mt][0] = packbf(p00 - bf_lo(ph[mt][0]), p01 - bf_hi(ph[mt][0]));
                pl[mt][1] = packbf(p10 - bf_lo(ph[mt][1]), p11 - bf_hi(ph[mt][1]));
                pl[mt][2] = packbf(p20 - bf_lo(ph[mt][2]), p21 - bf_hi(ph[mt][2]));
                pl[mt][3] = packbf(p30 - bf_lo(ph[mt][3]), p31 - bf_hi(ph[mt][3]));
            }
#pragma unroll
            for (int ndp = 0; ndp < 4; ndp++) {
                int row = kc * 16 + (lane & 7) + ((lane >> 3) & 1) * 8;
                uint32_t ch = (uint32_t)(2 * ndp + (lane >> 4));
                uint32_t off = (uint32_t)(row * 128) + ((ch ^ (uint32_t)(row & 7)) << 4);
                uint32_t bvh[4], bvl[4];
                ldm_x4t(bvh, sVh + off);
                ldm_x4t(bvl, sVl + off);
#pragma unroll
                for (int nt2 = 0; nt2 < 2; nt2++) {
                    const int nd = ndp * 2 + nt2;
#pragma unroll
                    for (int mt = 0; mt < 2; mt++) {
                        mma16816(Oacc[mt][nd], ph[mt], bvh[nt2*2], bvh[nt2*2+1]);
                        mma16816(Oacc[mt][nd], ph[mt], bvl[nt2*2], bvl[nt2*2+1]);
                        mma16816(Oacc[mt][nd], pl[mt], bvh[nt2*2], bvh[nt2*2+1]);
                    }
                }
            }
        }
    }

    // ---- epilogue: normalize, split to bf16 hi/lo, store ----
#pragma unroll
    for (int mt = 0; mt < 2; mt++)
#pragma unroll
        for (int rr = 0; rr < 2; rr++) {
            const int row = wid * 32 + mt * 16 + (lane >> 2) + rr * 8;
            const float inv = 1.f / l_i[mt][rr];
            const size_t rb = qbase + (size_t)row * E_ + (lane & 3) * 2;
#pragma unroll
            for (int nd = 0; nd < 8; nd++) {
                float v0 = Oacc[mt][nd][rr*2]   * inv;
                float v1 = Oacc[mt][nd][rr*2+1] * inv;
                uint32_t hp = packbf(v0, v1);
                uint32_t lp = packbf(v0 - bf_lo(hp), v1 - bf_hi(hp));
                *(uint32_t*)(Oh + rb + nd * 8) = hp;
                *(uint32_t*)(Ol + rb + nd * 8) = lp;
            }
        }
}

// ---------------------------------------------------------------------------
extern "C" void kernel_launch(void* const* d_in, const int* in_sizes, int n_in,
                              void* d_out, int out_size)
{
    const float* x  = (const float*)d_in[0];
    const float* Wq = (const float*)d_in[1];
    const float* bq = (const float*)d_in[2];
    const float* Wk = (const float*)d_in[3];
    const float* bk = (const float*)d_in[4];
    const float* Wv = (const float*)d_in[5];
    const float* bv = (const float*)d_in[6];
    const float* Wo = (const float*)d_in[7];
    const float* bo = (const float*)d_in[8];
    float* out = (float*)d_out;

    __nv_bfloat16 *xh, *xl, *qh, *ql, *kh, *kl, *vh, *vl, *ah, *al;
    __nv_bfloat16 *wqh, *wql, *wkh, *wkl, *wvh, *wvl, *woh, *wol;
    cudaGetSymbolAddress((void**)&xh, g_xh);
    cudaGetSymbolAddress((void**)&xl, g_xl);
    cudaGetSymbolAddress((void**)&qh, g_qh);
    cudaGetSymbolAddress((void**)&ql, g_ql);
    cudaGetSymbolAddress((void**)&kh, g_kh);
    cudaGetSymbolAddress((void**)&kl, g_kl);
    cudaGetSymbolAddress((void**)&vh, g_vh);
    cudaGetSymbolAddress((void**)&vl, g_vl);
    cudaGetSymbolAddress((void**)&ah, g_ah);
    cudaGetSymbolAddress((void**)&al, g_al);
    cudaGetSymbolAddress((void**)&wqh, g_wqh);
    cudaGetSymbolAddress((void**)&wql, g_wql);
    cudaGetSymbolAddress((void**)&wkh, g_wkh);
    cudaGetSymbolAddress((void**)&wkl, g_wkl);
    cudaGetSymbolAddress((void**)&wvh, g_wvh);
    cudaGetSymbolAddress((void**)&wvl, g_wvl);
    cudaGetSymbolAddress((void**)&woh, g_woh);
    cudaGetSymbolAddress((void**)&wol, g_wol);

    cudaFuncSetAttribute(gemm_split_hmma<true>,
                         cudaFuncAttributeMaxDynamicSharedMemorySize, 2 * STG);
    cudaFuncSetAttribute(gemm_split_hmma<false>,
                         cudaFuncAttributeMaxDynamicSharedMemorySize, 2 * STG);
    cudaFuncSetAttribute(flash_hmma,
                         cudaFuncAttributeMaxDynamicSharedMemorySize, FA_SMEM);

    const int n4x = (M_ * E_) / 4;
    const int n4w = (E_ * E_) / 4;
    split_f32<<<(n4x + 255) / 256, 256>>>(x,  xh,  xl,  n4x);
    split_f32<<<(n4w + 255) / 256, 256>>>(Wq, wqh, wql, n4w);
    split_f32<<<(n4w + 255) / 256, 256>>>(Wk, wkh, wkl, n4w);
    split_f32<<<(n4w + 255) / 256, 256>>>(Wv, wvh, wvl, n4w);
    split_f32<<<(n4w + 255) / 256, 256>>>(Wo, woh, wol, n4w);

    dim3 gg(E_ / 128, M_ / 128);   // (16, 32)
    gemm_split_hmma<true><<<gg, 256, 2 * STG>>>(xh, xl, wqh, wql, bq, nullptr, qh, ql);
    gemm_split_hmma<true><<<gg, 256, 2 * STG>>>(xh, xl, wkh, wkl, bk, nullptr, kh, kl);
    gemm_split_hmma<true><<<gg, 256, 2 * STG>>>(xh, xl, wvh, wvl, bv, nullptr, vh, vl);

    dim3 ga(S_ / FQT, B_ * H_);    // (8, 64)
    flash_hmma<<<ga, 256, FA_SMEM>>>(qh, ql, kh, kl, vh, vl, ah, al);

    gemm_split_hmma<false><<<gg, 256, 2 * STG>>>(ah, al, woh, wol, bo, out, nullptr, nullptr);
}